// round 10
// baseline (speedup 1.0000x reference)
#include <cuda_runtime.h>
#include <cuda_bf16.h>
#include <cfloat>

// RegionSelector: B=128, C=1, H=W=512, GRID=4 (128x128 cells), WIN=3 -> 2x2
// windows, TOPK=1. One block per batch image.
//
// Output convention: the harness's __output__ dtype is float32 (the checker
// reads d_out as floats), so the integer (row, col) coordinates are written
// as float values 0.0f / 1.0f.
//
// Warp w (of 16) owns rows [w*32, w*32+32) -- entirely inside grid row w>>2.
// Lane l loads float4 indices l, l+32, l+64, l+96 of each row -- entirely
// inside grid cols 0,1,2,3 respectively -> 4 register accumulators per lane.
__global__ __launch_bounds__(512) void rs_kernel(const float* __restrict__ in,
                                                 float* __restrict__ out) {
    const int b    = blockIdx.x;
    const int tid  = threadIdx.x;
    const int w    = tid >> 5;
    const int lane = tid & 31;

    const float* base = in + (size_t)b * 512 * 512;
    const int row0 = w * 32;

    float a0 = 0.f, a1 = 0.f, a2 = 0.f, a3 = 0.f;
    #pragma unroll 4
    for (int r = 0; r < 32; ++r) {
        const float4* rowp = (const float4*)(base + (size_t)(row0 + r) * 512);
        float4 v0 = rowp[lane];
        float4 v1 = rowp[lane + 32];
        float4 v2 = rowp[lane + 64];
        float4 v3 = rowp[lane + 96];
        a0 += (v0.x + v0.y) + (v0.z + v0.w);
        a1 += (v1.x + v1.y) + (v1.z + v1.w);
        a2 += (v2.x + v2.y) + (v2.z + v2.w);
        a3 += (v3.x + v3.y) + (v3.z + v3.w);
    }

    #pragma unroll
    for (int o = 16; o; o >>= 1) {
        a0 += __shfl_xor_sync(0xffffffffu, a0, o);
        a1 += __shfl_xor_sync(0xffffffffu, a1, o);
        a2 += __shfl_xor_sync(0xffffffffu, a2, o);
        a3 += __shfl_xor_sync(0xffffffffu, a3, o);
    }

    __shared__ float sm[16][4];       // [warp(row band)][grid col]
    if (lane == 0) {
        sm[w][0] = a0; sm[w][1] = a1; sm[w][2] = a2; sm[w][3] = a3;
    }
    __syncthreads();

    if (tid == 0) {
        // Combine the 4 warps of each grid-row band; mean divide (argmax-
        // invariant but mirrors the reference).
        float cell[4][4];
        #pragma unroll
        for (int gr = 0; gr < 4; ++gr)
            #pragma unroll
            for (int gc = 0; gc < 4; ++gc)
                cell[gr][gc] = (sm[gr * 4 + 0][gc] + sm[gr * 4 + 1][gc] +
                                sm[gr * 4 + 2][gc] + sm[gr * 4 + 3][gc]) *
                               (1.0f / 16384.0f);

        float best = -FLT_MAX;
        int best_idx = 0;
        #pragma unroll
        for (int wr = 0; wr < 2; ++wr)
            #pragma unroll
            for (int wc = 0; wc < 2; ++wc) {
                float s = 0.f;
                #pragma unroll
                for (int r = 0; r < 3; ++r)
                    #pragma unroll
                    for (int c = 0; c < 3; ++c)
                        s += cell[wr + r][wc + c];
                const int idx = wr * 2 + wc;
                if (s > best) { best = s; best_idx = idx; }  // first-max == top_k
            }

        out[b * 2 + 0] = (float)(best_idx >> 1);   // row = idx // 2
        out[b * 2 + 1] = (float)(best_idx & 1);    // col = idx %  2
    }
}

extern "C" void kernel_launch(void* const* d_in, const int* in_sizes, int n_in,
                              void* d_out, int out_size) {
    const float* in = (const float*)d_in[0];
    float* out = (float*)d_out;
    rs_kernel<<<128, 512>>>(in, out);
}